// round 3
// baseline (speedup 1.0000x reference)
#include <cuda_runtime.h>

#define NBLOCKS 1184   // 148 SMs x 8 CTAs -> exactly one wave at 256 thr / <=32 regs
#define NTHREADS 256

// Module-load zero-initialized; last block resets g_count each call so every
// graph replay starts clean. Partials are fully overwritten each call.
__device__ float g_partials[NBLOCKS];
__device__ unsigned int g_count = 0u;

__device__ __forceinline__ float skew_elem(float p, float t) {
    float d   = p - t;                 // y_pred - y_true
    float lam = (t - 50.0f) * 0.02f;   // both lamda branches collapse to (t-50)/50
    // gate==1  <=>  sign(y_true - y_pred)*sign(lam)==1  <=>  d*lam < 0
    float arg = (d * lam < 0.0f) ? fabsf(lam) : 0.0f;
    return fabsf(d) * __expf(arg);     // __expf(0) == 1 exactly
}

__global__ void __launch_bounds__(NTHREADS)
skew_fused_kernel(const float4* __restrict__ yp,
                  const float4* __restrict__ yt,
                  float* __restrict__ out,
                  int n4, float inv_n) {
    float s = 0.0f;
    int idx    = blockIdx.x * NTHREADS + threadIdx.x;
    int stride = gridDim.x * NTHREADS;
    #pragma unroll 2
    for (int i = idx; i < n4; i += stride) {
        float4 p = yp[i];
        float4 t = yt[i];
        s += skew_elem(p.x, t.x);
        s += skew_elem(p.y, t.y);
        s += skew_elem(p.z, t.z);
        s += skew_elem(p.w, t.w);
    }

    // warp reduce
    #pragma unroll
    for (int o = 16; o > 0; o >>= 1)
        s += __shfl_xor_sync(0xffffffffu, s, o);

    __shared__ float warp_sums[NTHREADS / 32];
    __shared__ bool is_last;
    int lane = threadIdx.x & 31;
    int wid  = threadIdx.x >> 5;
    if (lane == 0) warp_sums[wid] = s;
    __syncthreads();

    if (threadIdx.x == 0) {
        float v = warp_sums[0];
        #pragma unroll
        for (int w = 1; w < NTHREADS / 32; w++) v += warp_sums[w];
        g_partials[blockIdx.x] = v;         // plain store, no atomic
        __threadfence();
        unsigned int done = atomicAdd(&g_count, 1u);
        is_last = (done == gridDim.x - 1);
    }
    __syncthreads();

    if (is_last) {
        // All 256 threads of the final block reduce the per-block partials
        // in double precision.
        double d = 0.0;
        for (int i = threadIdx.x; i < (int)gridDim.x; i += NTHREADS)
            d += (double)g_partials[i];
        #pragma unroll
        for (int o = 16; o > 0; o >>= 1)
            d += __shfl_xor_sync(0xffffffffu, d, o);

        __shared__ double dsum[NTHREADS / 32];
        if (lane == 0) dsum[wid] = d;
        __syncthreads();
        if (threadIdx.x == 0) {
            double total = dsum[0];
            #pragma unroll
            for (int w = 1; w < NTHREADS / 32; w++) total += dsum[w];
            out[0] = (float)(total * (double)inv_n);
            g_count = 0u;                   // reset for next graph replay
        }
    }
}

extern "C" void kernel_launch(void* const* d_in, const int* in_sizes, int n_in,
                              void* d_out, int out_size) {
    const float4* yp = (const float4*)d_in[0];  // y_pred
    const float4* yt = (const float4*)d_in[1];  // y_true
    float* out = (float*)d_out;

    int n  = in_sizes[0];       // 8388608
    int n4 = n >> 2;            // 2097152, exact

    int blocks = NBLOCKS;
    if (blocks * NTHREADS > n4 && n4 > 0)
        blocks = (n4 + NTHREADS - 1) / NTHREADS;

    skew_fused_kernel<<<blocks, NTHREADS>>>(yp, yt, out, n4, 1.0f / (float)n);
}